// round 3
// baseline (speedup 1.0000x reference)
#include <cuda_runtime.h>

// Problem constants (fixed by the reference):
#define TT 512          // time steps
#define NB 32           // batch
#define CC 8000         // classes
#define SS 40           // max target length
#define SE 81           // 2*SS + 1 expanded-with-blank length
#define SPR 128         // padded scratch row: 32 lanes * 4 floats (16B per lane)
#define LANES 27        // 27 lanes * 3 slots = 81 slots

#define LOG_TINY (-87.336544f)   // log(float32 tiny), matches reference
#define NEGBIG   (-1e30f)        // "minus infinity" sentinel for LSE

// Compact gathered log-probs: [NB][TT][32 lanes][4 floats]. 8 MB, L2-resident.
// __device__ globals are zero-initialized, so pad entries are benign.
__device__ float g_lp[(size_t)NB * TT * SPR];

// ---------------------------------------------------------------------------
// Kernel 1: gather log_probs[t, n, et[s]] into padded per-lane layout.
// et[s] = blank(0) for even s, targets[n, s>>1] for odd s.
// ---------------------------------------------------------------------------
__global__ void ctc_gather_kernel(const float* __restrict__ lp,
                                  const int* __restrict__ tg) {
    int idx = blockIdx.x * blockDim.x + threadIdx.x;
    const int total = NB * TT * SE;
    if (idx >= total) return;
    int s = idx % SE;
    int r = idx / SE;
    int t = r % TT;
    int n = r / TT;
    int c = (s & 1) ? tg[n * SS + (s >> 1)] : 0;
    float v = lp[(size_t)t * (NB * CC) + (size_t)n * CC + c];
    g_lp[((size_t)n * TT + t) * SPR + (s / 3) * 4 + (s % 3)] = v;
}

// 3-way log-sum-exp. With z (or y,z) = NEGBIG this degrades exactly to the
// 2-way / identity cases: expf(NEGBIG - m) == 0, logf(1) == 0.
__device__ __forceinline__ float lsum3(float x, float y, float z) {
    float m = fmaxf(x, fmaxf(y, z));
    float e = __expf(x - m) + __expf(y - m) + __expf(z - m);
    return m + __logf(e);
}

// ---------------------------------------------------------------------------
// Kernel 2: alpha recursion. One warp per batch item; lane l owns slots
// 3l, 3l+1, 3l+2. Cross-lane deps (s-1, s-2 for the lane's first slot) come
// from lane l-1's a2, a1 via shfl_up. lp rows prefetched 3 steps ahead.
// ---------------------------------------------------------------------------
__global__ void __launch_bounds__(32, 1)
ctc_rec_kernel(const int* __restrict__ tg,
               const int* __restrict__ tlen,
               float* __restrict__ out) {
    const int n = blockIdx.x;
    const int lane = threadIdx.x;
    const float4* lpn = (const float4*)(g_lp + (size_t)n * TT * SPR);

    const int s0 = lane * 3;

    // Skip-transition flags (precomputed, loop-invariant):
    // skip allowed at slot s iff s odd, s>=3, and targets differ two back.
    bool k0 = false, k1 = false, k2 = false;
    {
        int s = s0;
        if (s < SE && s >= 3 && (s & 1))
            k0 = (tg[n * SS + (s >> 1)] != tg[n * SS + (s >> 1) - 1]);
        s = s0 + 1;
        if (s < SE && s >= 3 && (s & 1))
            k1 = (tg[n * SS + (s >> 1)] != tg[n * SS + (s >> 1) - 1]);
        s = s0 + 2;
        if (s < SE && s >= 3 && (s & 1))
            k2 = (tg[n * SS + (s >> 1)] != tg[n * SS + (s >> 1) - 1]);
    }

    // alpha0: slot0 = lp(0, blank), slot1 = lp(0, target0), rest LOG_TINY.
    float a0 = LOG_TINY, a1 = LOG_TINY, a2 = LOG_TINY;
    {
        float4 q0 = lpn[lane];     // row t=0
        if (lane == 0) { a0 = q0.x; a1 = q0.y; }
    }

    // Software pipeline: 3-deep lp prefetch ring (rows t+1..t+3 in flight).
    float4 pf0 = lpn[1 * 32 + lane];
    float4 pf1 = lpn[2 * 32 + lane];
    float4 pf2 = lpn[3 * 32 + lane];

    for (int t = 1; t < TT; ++t) {
        float4 cur = pf0;
        pf0 = pf1;
        pf1 = pf2;
        int tn = t + 3;
        if (tn > TT - 1) tn = TT - 1;      // redundant tail reloads, harmless
        pf2 = lpn[tn * 32 + lane];

        // Old alpha[s0-1], alpha[s0-2] live in lane-1's a2, a1.
        float pm1 = __shfl_up_sync(0xffffffffu, a2, 1);
        float pm2 = __shfl_up_sync(0xffffffffu, a1, 1);
        if (lane == 0) { pm1 = NEGBIG; pm2 = NEGBIG; }   // slot 0 has no s-1

        float n0 = lsum3(a0, pm1, k0 ? pm2 : NEGBIG) + cur.x;
        float n1 = lsum3(a1, a0,  k1 ? pm1 : NEGBIG) + cur.y;
        float n2 = lsum3(a2, a1,  k2 ? a0  : NEGBIG) + cur.z;

        a0 = n0; a1 = n1; a2 = n2;
    }

    // Final combine: loss = logadd(alpha[l-1], alpha[l-2]), l = 2*tl + 1.
    __shared__ float sa[96];
    sa[s0] = a0; sa[s0 + 1] = a1; sa[s0 + 2] = a2;
    __syncwarp();
    if (lane == 0) {
        int tl = tlen[n];
        int l = 2 * tl + 1;
        float x = sa[l - 1];
        float y = sa[l - 2];
        float m = fmaxf(x, y);
        float loss = m + log1pf(__expf(fminf(x, y) - m));
        out[n] = -loss / (float)tl;
    }
}

// ---------------------------------------------------------------------------
// Launch: gather (parallel) then recursion (32 warps). Default stream,
// graph-capturable, allocation-free (scratch is a __device__ global).
// Inputs: [0]=log_probs f32 (T,N,C), [1]=targets i32 (N,S),
//         [2]=input_lengths i32 (ignored, as in reference), [3]=target_lengths i32.
// ---------------------------------------------------------------------------
extern "C" void kernel_launch(void* const* d_in, const int* in_sizes, int n_in,
                              void* d_out, int out_size) {
    const float* log_probs  = (const float*)d_in[0];
    const int*   targets    = (const int*)d_in[1];
    const int*   tgt_lens   = (const int*)d_in[3];
    float*       out        = (float*)d_out;

    const int total = NB * TT * SE;
    ctc_gather_kernel<<<(total + 255) / 256, 256>>>(log_probs, targets);
    ctc_rec_kernel<<<NB, 32>>>(targets, tgt_lens, out);
}

// round 4
// speedup vs baseline: 2.2886x; 2.2886x over previous
#include <cuda_runtime.h>
#include <cstdint>

// Problem constants (fixed by the reference):
#define TT 512          // time steps
#define NB 32           // batch
#define CC 8000         // classes
#define SS 40           // max target length
#define SE 81           // 2*SS + 1 expanded-with-blank length
#define DEPTH 16        // cp.async pipeline depth (rows in flight)

#define LOG2E 1.4426950408889634f
#define LN2   0.6931471805599453f
#define TINY2 (-126.0f)          // log2(float32 tiny) == LOG_TINY * log2(e)
#define NEG2  (-1e30f)           // "minus infinity" sentinel for LSE

__device__ __forceinline__ float ex2f(float x) {
    float r; asm("ex2.approx.ftz.f32 %0, %1;" : "=f"(r) : "f"(x)); return r;
}
__device__ __forceinline__ float lg2f(float x) {
    float r; asm("lg2.approx.f32 %0, %1;" : "=f"(r) : "f"(x)); return r;
}

// 3-way log-sum-exp in base-2. With z (or y,z) = NEG2 this degrades exactly
// to the 2-way / identity cases: ex2(NEG2 - m) flushes to 0, lg2(1) == 0.
__device__ __forceinline__ float lsum3_2(float x, float y, float z) {
    float m = fmaxf(fmaxf(x, y), z);
    float e = ex2f(x - m) + ex2f(y - m) + ex2f(z - m);
    return m + lg2f(e);
}

// One warp per batch item. Lane l owns slots 3l, 3l+1, 3l+2 (27 lanes cover
// all 81 slots). Cross-lane deps (s-1, s-2 of a lane's first slot) come from
// lane l-1's a2, a1 via shfl_up. The three log_probs entries a lane needs per
// time step live at loop-invariant class columns, so they are streamed
// directly from the big (T,N,C) tensor with a depth-16 cp.async ring —
// no gather kernel, no scratch, and the prefetch cannot be sunk by ptxas.
__global__ void __launch_bounds__(32, 1)
ctc_kernel(const float* __restrict__ lp,
           const int*   __restrict__ tg,
           const int*   __restrict__ tlen,
           float*       __restrict__ out)
{
    __shared__ float ring[DEPTH][3][32];   // [slot][class j][lane] - conflict free
    __shared__ float sa[96];

    const int n    = blockIdx.x;
    const int lane = threadIdx.x;
    const int s0   = lane * 3;

    // Loop-invariant class columns and skip-transition flags per owned slot.
    // et[s] = blank(0) for even s, targets[n, s>>1] for odd s.
    // skip allowed at slot s iff s odd, s>=3, and target differs from two back.
    int  c0 = 0, c1 = 0, c2 = 0;
    bool k0 = false, k1 = false, k2 = false;
    {
        int s;
        s = s0;
        if (s < SE && (s & 1)) { c0 = tg[n*SS + (s>>1)]; if (s >= 3) k0 = (c0 != tg[n*SS + (s>>1) - 1]); }
        s = s0 + 1;
        if (s < SE && (s & 1)) { c1 = tg[n*SS + (s>>1)]; if (s >= 3) k1 = (c1 != tg[n*SS + (s>>1) - 1]); }
        s = s0 + 2;
        if (s < SE && (s & 1)) { c2 = tg[n*SS + (s>>1)]; if (s >= 3) k2 = (c2 != tg[n*SS + (s>>1) - 1]); }
    }

    const size_t stride = (size_t)NB * CC;            // elements per time step
    const float* p0 = lp + (size_t)n * CC + c0;
    const float* p1 = lp + (size_t)n * CC + c1;
    const float* p2 = lp + (size_t)n * CC + c2;

    // Prologue: issue rows 0..DEPTH-1, one commit-group per row.
    #pragma unroll
    for (int d = 0; d < DEPTH; ++d) {
        uint32_t d0 = (uint32_t)__cvta_generic_to_shared(&ring[d][0][lane]);
        uint32_t d1 = (uint32_t)__cvta_generic_to_shared(&ring[d][1][lane]);
        uint32_t d2 = (uint32_t)__cvta_generic_to_shared(&ring[d][2][lane]);
        const float* g0 = p0 + (size_t)d * stride;
        const float* g1 = p1 + (size_t)d * stride;
        const float* g2 = p2 + (size_t)d * stride;
        asm volatile(
            "cp.async.ca.shared.global [%0], [%3], 4;\n\t"
            "cp.async.ca.shared.global [%1], [%4], 4;\n\t"
            "cp.async.ca.shared.global [%2], [%5], 4;\n\t"
            "cp.async.commit_group;\n\t"
            :: "r"(d0), "r"(d1), "r"(d2), "l"(g0), "l"(g1), "l"(g2)
            : "memory");
    }

    // alpha0 (base-2 domain): slot0 = lp(0,blank), slot1 = lp(0,target0).
    float a0 = TINY2, a1 = TINY2, a2 = TINY2;
    asm volatile("cp.async.wait_group %0;" :: "n"(DEPTH - 1) : "memory");
    if (lane == 0) {
        a0 = ring[0][0][0] * LOG2E;   // each thread reads bytes it copied itself
        a1 = ring[0][1][0] * LOG2E;
    }

    for (int t = 1; t < TT; ++t) {
        // Prefetch row t+DEPTH-1 into slot (t-1)&15 (consumed last iteration).
        int tn = t + DEPTH - 1;
        if (tn < TT) {
            int slot = tn & (DEPTH - 1);
            uint32_t d0 = (uint32_t)__cvta_generic_to_shared(&ring[slot][0][lane]);
            uint32_t d1 = (uint32_t)__cvta_generic_to_shared(&ring[slot][1][lane]);
            uint32_t d2 = (uint32_t)__cvta_generic_to_shared(&ring[slot][2][lane]);
            const float* g0 = p0 + (size_t)tn * stride;
            const float* g1 = p1 + (size_t)tn * stride;
            const float* g2 = p2 + (size_t)tn * stride;
            asm volatile(
                "cp.async.ca.shared.global [%0], [%3], 4;\n\t"
                "cp.async.ca.shared.global [%1], [%4], 4;\n\t"
                "cp.async.ca.shared.global [%2], [%5], 4;\n\t"
                :: "r"(d0), "r"(d1), "r"(d2), "l"(g0), "l"(g1), "l"(g2)
                : "memory");
        }
        asm volatile("cp.async.commit_group;" ::: "memory");
        // committed = DEPTH + t; allow DEPTH-1 outstanding => rows 0..t done.
        asm volatile("cp.async.wait_group %0;" :: "n"(DEPTH - 1) : "memory");

        const int slot = t & (DEPTH - 1);
        float l0 = ring[slot][0][lane] * LOG2E;   // off critical path
        float l1 = ring[slot][1][lane] * LOG2E;
        float l2 = ring[slot][2][lane] * LOG2E;

        // Old alpha[s0-1], alpha[s0-2] live in lane-1's a2, a1.
        float pm1 = __shfl_up_sync(0xffffffffu, a2, 1);
        float pm2 = __shfl_up_sync(0xffffffffu, a1, 1);
        if (lane == 0) { pm1 = NEG2; pm2 = NEG2; }   // slot 0 has no s-1

        float n0 = lsum3_2(a0, pm1, k0 ? pm2 : NEG2) + l0;
        float n1 = lsum3_2(a1, a0,  k1 ? pm1 : NEG2) + l1;
        float n2 = lsum3_2(a2, a1,  k2 ? a0  : NEG2) + l2;

        a0 = n0; a1 = n1; a2 = n2;
    }

    // Final combine: loss = logadd(alpha[l-1], alpha[l-2]), l = 2*tl + 1,
    // converted back to natural log.
    sa[s0] = a0; sa[s0 + 1] = a1; sa[s0 + 2] = a2;
    __syncwarp();
    if (lane == 0) {
        int tl = tlen[n];
        int l  = 2 * tl + 1;
        float x = sa[l - 1];
        float y = sa[l - 2];
        float m = fmaxf(x, y);
        float s2 = m + lg2f(1.0f + ex2f(fminf(x, y) - m));
        out[n] = -(s2 * LN2) / (float)tl;
    }
}

// ---------------------------------------------------------------------------
// Inputs: [0]=log_probs f32 (T,N,C), [1]=targets i32 (N,S),
//         [2]=input_lengths i32 (ignored, as in reference), [3]=target_lengths i32.
// Single kernel, graph-capturable, allocation-free.
// ---------------------------------------------------------------------------
extern "C" void kernel_launch(void* const* d_in, const int* in_sizes, int n_in,
                              void* d_out, int out_size) {
    const float* log_probs = (const float*)d_in[0];
    const int*   targets   = (const int*)d_in[1];
    const int*   tgt_lens  = (const int*)d_in[3];
    float*       out       = (float*)d_out;

    ctc_kernel<<<NB, 32>>>(log_probs, targets, tgt_lens, out);
}

// round 5
// speedup vs baseline: 3.0917x; 1.3509x over previous
#include <cuda_runtime.h>
#include <cstdint>

// Problem constants (fixed by the reference):
#define TT 512          // time steps
#define NB 32           // batch
#define CC 8000         // classes
#define SS 40           // max target length
#define SE 81           // 2*SS + 1 expanded-with-blank length
#define DEPTH 16        // register-ring prefetch depth (rows in flight)

#define LOG2E 1.4426950408889634f
#define LN2   0.6931471805599453f
#define TINY2 (-126.0f)          // log2(float32 tiny) == log(tiny) * log2(e)
#define NEG2  (-1e30f)           // "minus infinity" sentinel for LSE

__device__ __forceinline__ float ex2f(float x) {
    float r; asm("ex2.approx.ftz.f32 %0, %1;" : "=f"(r) : "f"(x)); return r;
}
__device__ __forceinline__ float lg2f(float x) {
    float r; asm("lg2.approx.f32 %0, %1;" : "=f"(r) : "f"(x)); return r;
}

// Volatile LDG: cannot be deleted or sunk to the consumer by the frontend;
// result lands in a named register of the ring.
#define LDGV(dst, addr) \
    asm volatile("ld.global.nc.f32 %0, [%1];" : "=f"(dst) : "l"(addr))

// 3-way log-sum-exp in base-2, max-term skipped (ex2(0)==1 exactly, so this
// is value-identical to summing all three exps). NEG2 args flush to 0.
__device__ __forceinline__ float lse3(float x, float y, float z) {
    float hi  = fmaxf(x, y);
    float lo  = fminf(x, y);
    float m   = fmaxf(hi, z);
    float mid = fminf(hi, z);
    float e   = ex2f(lo - m) + ex2f(mid - m);
    return m + lg2f(1.0f + e);
}

// One warp per batch item. Lane l owns slots 3l, 3l+1, 3l+2 (27 lanes cover
// all 81 slots). Cross-lane deps (s-1, s-2 of a lane's first slot) come from
// lane l-1's a2, a1 via shfl_up. Each lane's three log_probs columns are
// loop-invariant classes, streamed with a depth-16 *register* ring of
// volatile LDGs (no smem, no cp.async waits). Loop unrolled x16 so ring
// indices are compile-time constants (stays in registers).
__global__ void __launch_bounds__(32, 1)
ctc_kernel(const float* __restrict__ lp,
           const int*   __restrict__ tg,
           const int*   __restrict__ tlen,
           float*       __restrict__ out)
{
    __shared__ float sa[96];

    const int n    = blockIdx.x;
    const int lane = threadIdx.x;
    const int s0   = lane * 3;

    // Loop-invariant class columns and skip-transition flags per owned slot.
    // et[s] = blank(0) for even s, targets[n, s>>1] for odd s.
    // skip allowed at slot s iff s odd, s>=3, and target differs from two back.
    int  c0 = 0, c1 = 0, c2 = 0;
    bool k0 = false, k1 = false, k2 = false;
    {
        int s;
        s = s0;
        if (s < SE && (s & 1)) { c0 = tg[n*SS + (s>>1)]; if (s >= 3) k0 = (c0 != tg[n*SS + (s>>1) - 1]); }
        s = s0 + 1;
        if (s < SE && (s & 1)) { c1 = tg[n*SS + (s>>1)]; if (s >= 3) k1 = (c1 != tg[n*SS + (s>>1) - 1]); }
        s = s0 + 2;
        if (s < SE && (s & 1)) { c2 = tg[n*SS + (s>>1)]; if (s >= 3) k2 = (c2 != tg[n*SS + (s>>1) - 1]); }
    }

    const size_t stride = (size_t)NB * CC;     // elements per time step
    const float* bp = lp + (size_t)n * CC;     // row-0 base for this batch item

    // Row-0 values for alpha init (issued first so latency overlaps prologue).
    float i0 = __ldg(bp);          // blank at t=0
    float i1 = __ldg(bp + c1);     // lane 0's slot 1 class at t=0

    // Prologue: rows 1..DEPTH into ring slots 0..DEPTH-1 (slot = (t-1)&15).
    float rg0[DEPTH], rg1[DEPTH], rg2[DEPTH];
    #pragma unroll
    for (int d = 0; d < DEPTH; ++d) {
        const float* r = bp + (size_t)(d + 1) * stride;
        LDGV(rg0[d], r + c0);
        LDGV(rg1[d], r + c1);
        LDGV(rg2[d], r + c2);
    }

    // alpha0 (base-2 domain): slot0 = lp(0,blank), slot1 = lp(0,target0).
    float a0 = TINY2, a1 = TINY2, a2 = TINY2;
    if (lane == 0) { a0 = i0 * LOG2E; a1 = i1 * LOG2E; }

    // One recursion step for time t, ring slot d (compile-time constant),
    // with prefetch of row min(t+DEPTH, TT-1) back into slot d.
    #define STEP(d, t, DO_LOAD)                                           \
    {                                                                     \
        float l0 = rg0[d], l1 = rg1[d], l2 = rg2[d];                      \
        if (DO_LOAD) {                                                    \
            int tn = (t) + DEPTH; if (tn > TT - 1) tn = TT - 1;           \
            const float* r = bp + (size_t)tn * stride;                    \
            LDGV(rg0[d], r + c0);                                         \
            LDGV(rg1[d], r + c1);                                         \
            LDGV(rg2[d], r + c2);                                         \
        }                                                                 \
        float pm1 = __shfl_up_sync(0xffffffffu, a2, 1);                   \
        float pm2 = __shfl_up_sync(0xffffffffu, a1, 1);                   \
        if (lane == 0) { pm1 = NEG2; pm2 = NEG2; }                        \
        float z0 = k0 ? pm2 : NEG2;                                       \
        float z1 = k1 ? pm1 : NEG2;                                       \
        float z2 = k2 ? a0  : NEG2;                                       \
        float t0 = lse3(a0, pm1, z0);                                     \
        float t1 = lse3(a1, a0,  z1);                                     \
        float t2 = lse3(a2, a1,  z2);                                     \
        a0 = fmaf(l0, LOG2E, t0);                                         \
        a1 = fmaf(l1, LOG2E, t1);                                         \
        a2 = fmaf(l2, LOG2E, t2);                                         \
    }

    // Main: t = 1..496 in 31 blocks of 16; slot index == d because tb ≡ 1 (mod 16).
    for (int tb = 1; tb <= TT - 1 - 2 * (DEPTH - 1); tb += DEPTH) {
        #pragma unroll
        for (int d = 0; d < DEPTH; ++d) {
            STEP(d, tb + d, true);
        }
    }
    // Tail: t = 497..511, rows already in flight, no more loads.
    {
        const int tb = TT - (DEPTH - 1);    // 497
        #pragma unroll
        for (int d = 0; d < DEPTH - 1; ++d) {
            STEP(d, tb + d, false);
        }
    }
    #undef STEP

    // Final combine: loss = logadd(alpha[l-1], alpha[l-2]), l = 2*tl + 1,
    // converted back to natural log.
    sa[s0] = a0; sa[s0 + 1] = a1; sa[s0 + 2] = a2;
    __syncwarp();
    if (lane == 0) {
        int tl = tlen[n];
        int l  = 2 * tl + 1;
        float x = sa[l - 1];
        float y = sa[l - 2];
        float m = fmaxf(x, y);
        float s2 = m + lg2f(1.0f + ex2f(fminf(x, y) - m));
        out[n] = -(s2 * LN2) / (float)tl;
    }
}

// ---------------------------------------------------------------------------
// Inputs: [0]=log_probs f32 (T,N,C), [1]=targets i32 (N,S),
//         [2]=input_lengths i32 (ignored, as in reference), [3]=target_lengths i32.
// Single kernel, graph-capturable, allocation-free.
// ---------------------------------------------------------------------------
extern "C" void kernel_launch(void* const* d_in, const int* in_sizes, int n_in,
                              void* d_out, int out_size) {
    const float* log_probs = (const float*)d_in[0];
    const int*   targets   = (const int*)d_in[1];
    const int*   tgt_lens  = (const int*)d_in[3];
    float*       out       = (float*)d_out;

    ctc_kernel<<<NB, 32>>>(log_probs, targets, tgt_lens, out);
}